// round 2
// baseline (speedup 1.0000x reference)
#include <cuda_runtime.h>
#include <cuda_bf16.h>
#include <math.h>

#define N_TOK 1024
#define HDIM  2048
#define IDIM  1408
#define NEXP  8
#define TOPK  2
#define ISH   2816
#define NSLOT (N_TOK * TOPK)   // 2048

#define BM 128
#define BN 128
#define BK 16
#define PAD 4                   // smem row stride 132 floats

// ---------------- scratch (static device memory; no allocations) ----------------
__device__ int   d_cnt[NEXP];
__device__ int   d_cnt2[NEXP];
__device__ int   d_off[NEXP];
__device__ int   d_sel[N_TOK * TOPK];
__device__ float d_selw[N_TOK * TOPK];
__device__ int   d_tok[NSLOT];
__device__ float d_wt[NSLOT];
// buf1: shared-gate activations, then routed-gate activations (reused sequentially)
// buf2: shared-up activations, then routed-up activations
__device__ float d_buf1[(size_t)NSLOT * IDIM];   // 2048*1408 == 1024*2816
__device__ float d_buf2[(size_t)NSLOT * IDIM];

// ---------------- helpers: packed f32x2 FMA (Blackwell) ----------------
__device__ __forceinline__ unsigned long long pack2f(float v) {
    unsigned long long r;
    unsigned int u = __float_as_uint(v);
    asm("mov.b64 %0, {%1, %1};" : "=l"(r) : "r"(u));
    return r;
}
__device__ __forceinline__ void ffma2(unsigned long long& c,
                                      unsigned long long a,
                                      unsigned long long b) {
    asm("fma.rn.f32x2 %0, %1, %2, %0;" : "+l"(c) : "l"(a), "l"(b));
}

// ---------------- small kernels ----------------
__global__ void zero_kernel() {
    int t = threadIdx.x;
    if (t < NEXP) { d_cnt[t] = 0; d_cnt2[t] = 0; }
}

// 1 block per token; 8 warps = 8 experts
__global__ void router_kernel(const float* __restrict__ x,
                              const float* __restrict__ gw) {
    int n    = blockIdx.x;
    int wid  = threadIdx.x >> 5;
    int lane = threadIdx.x & 31;
    __shared__ float logits[NEXP];
    const float* xr = x  + (size_t)n   * HDIM;
    const float* gr = gw + (size_t)wid * HDIM;
    float s = 0.f;
    for (int h = lane; h < HDIM; h += 32) s = fmaf(xr[h], gr[h], s);
    #pragma unroll
    for (int o = 16; o > 0; o >>= 1) s += __shfl_xor_sync(0xffffffffu, s, o);
    if (lane == 0) logits[wid] = s;
    __syncthreads();
    if (threadIdx.x == 0) {
        float mx = logits[0];
        #pragma unroll
        for (int e = 1; e < NEXP; ++e) mx = fmaxf(mx, logits[e]);
        float p[NEXP]; float sum = 0.f;
        #pragma unroll
        for (int e = 0; e < NEXP; ++e) { p[e] = expf(logits[e] - mx); sum += p[e]; }
        float inv = 1.f / sum;
        #pragma unroll
        for (int e = 0; e < NEXP; ++e) p[e] *= inv;
        // top-2 (first occurrence wins on ties, matching lax.top_k)
        float p1 = p[0]; int i1 = 0;
        float p2 = -1.f; int i2 = -1;
        #pragma unroll
        for (int e = 1; e < NEXP; ++e) {
            if (p[e] > p1)      { p2 = p1; i2 = i1; p1 = p[e]; i1 = e; }
            else if (p[e] > p2) { p2 = p[e]; i2 = e; }
        }
        float ws = p1 + p2 + 1e-20f;
        float w1 = p1 / ws, w2 = p2 / ws;
        d_sel[n * 2]      = i1; d_selw[n * 2]     = w1;
        d_sel[n * 2 + 1]  = i2; d_selw[n * 2 + 1] = w2;
        atomicAdd(&d_cnt[i1], 1);
        atomicAdd(&d_cnt[i2], 1);
    }
}

__global__ void offsets_kernel() {
    if (threadIdx.x == 0) {
        int acc = 0;
        #pragma unroll
        for (int e = 0; e < NEXP; ++e) { d_off[e] = acc; acc += d_cnt[e]; }
    }
}

__global__ void scatter_kernel() {
    int n = blockIdx.x * blockDim.x + threadIdx.x;
    if (n >= N_TOK) return;
    #pragma unroll
    for (int k = 0; k < TOPK; ++k) {
        int   e = d_sel[n * 2 + k];
        float w = d_selw[n * 2 + k];
        int pos  = atomicAdd(&d_cnt2[e], 1);
        int slot = d_off[e] + pos;
        d_tok[slot] = n;
        d_wt[slot]  = w;
    }
}

__global__ void silu_mul_kernel(const float* __restrict__ g,
                                const float* __restrict__ u,
                                float* __restrict__ o, int n) {
    int i = blockIdx.x * blockDim.x + threadIdx.x;
    if (i >= n) return;
    float gv = g[i];
    float s  = gv / (1.f + expf(-gv));
    o[i] = s * u[i];
}

// ---------------- the NT-SGEMM: C[m,n] = sum_k A[m,k] * B[n,k] ----------------
// MODE 0: plain A (row m), plain store C[m*N+n]
// MODE 1: routed GEMM1: per-expert (blockIdx.z), A rows gathered via d_tok,
//         store C[(off+m)*N+n]
// MODE 2: routed GEMM2: per-expert, A rows = slots (off+m), epilogue:
//         atomicAdd(out[tok*N+n], wt * acc)
template <int MODE>
__global__ __launch_bounds__(256, 2)
void gemm_nt(const float* __restrict__ A, const float* __restrict__ B,
             float* __restrict__ C, int M, int N, int K) {
    int e = blockIdx.z;
    int base = 0;
    if (MODE >= 1) {
        M    = d_cnt[e];
        base = d_off[e];
        B   += (size_t)e * N * K;
    }
    int m0 = blockIdx.y * BM;
    if (m0 >= M) return;
    int n0 = blockIdx.x * BN;

    __shared__ __align__(16) float As[BK][BM + PAD];
    __shared__ __align__(16) float Bs[BK][BN + PAD];

    int t     = threadIdx.x;
    int lrow  = t >> 2;          // 0..63
    int lk4   = (t & 3) * 4;     // 0,4,8,12
    int tx4   = (t & 15) * 4;
    int ty4   = (t >> 4) * 4;

    const float* aptr[2];
    bool avalid[2];
    #pragma unroll
    for (int it = 0; it < 2; ++it) {
        int m = m0 + lrow + it * 64;
        bool v = (m < M);
        int row;
        if (MODE == 1)      row = v ? d_tok[base + m] : 0;
        else if (MODE == 2) row = v ? (base + m) : 0;
        else                row = v ? m : 0;
        aptr[it]   = A + (size_t)row * K;
        avalid[it] = v;
    }
    const float* bptr[2];
    #pragma unroll
    for (int it = 0; it < 2; ++it)
        bptr[it] = B + (size_t)(n0 + lrow + it * 64) * K;

    unsigned long long acc[8][4];
    #pragma unroll
    for (int i = 0; i < 8; ++i)
        #pragma unroll
        for (int j = 0; j < 4; ++j) acc[i][j] = 0ull;

    const float4 z4 = make_float4(0.f, 0.f, 0.f, 0.f);
    float4 ra[2], rb[2];

    // prologue: tile 0
    #pragma unroll
    for (int it = 0; it < 2; ++it) {
        ra[it] = avalid[it] ? *(const float4*)(aptr[it] + lk4) : z4;
        rb[it] = *(const float4*)(bptr[it] + lk4);
    }
    #pragma unroll
    for (int it = 0; it < 2; ++it) {
        int r = lrow + it * 64;
        As[lk4 + 0][r] = ra[it].x; As[lk4 + 1][r] = ra[it].y;
        As[lk4 + 2][r] = ra[it].z; As[lk4 + 3][r] = ra[it].w;
        Bs[lk4 + 0][r] = rb[it].x; Bs[lk4 + 1][r] = rb[it].y;
        Bs[lk4 + 2][r] = rb[it].z; Bs[lk4 + 3][r] = rb[it].w;
    }
    __syncthreads();

    int KT = K / BK;
    for (int kt = 1; kt <= KT; ++kt) {
        bool has_next = (kt < KT);
        if (has_next) {
            int ko = kt * BK + lk4;
            #pragma unroll
            for (int it = 0; it < 2; ++it) {
                ra[it] = avalid[it] ? *(const float4*)(aptr[it] + ko) : z4;
                rb[it] = *(const float4*)(bptr[it] + ko);
            }
        }
        #pragma unroll
        for (int k = 0; k < BK; ++k) {
            float4 a0 = *(const float4*)&As[k][ty4];
            float4 a1 = *(const float4*)&As[k][64 + ty4];
            const unsigned long long* bp0 =
                reinterpret_cast<const unsigned long long*>(&Bs[k][tx4]);
            const unsigned long long* bp1 =
                reinterpret_cast<const unsigned long long*>(&Bs[k][64 + tx4]);
            unsigned long long pb0 = bp0[0], pb1 = bp0[1];
            unsigned long long pb2 = bp1[0], pb3 = bp1[1];
            float av[8] = {a0.x, a0.y, a0.z, a0.w, a1.x, a1.y, a1.z, a1.w};
            #pragma unroll
            for (int i = 0; i < 8; ++i) {
                unsigned long long pa = pack2f(av[i]);
                ffma2(acc[i][0], pa, pb0);
                ffma2(acc[i][1], pa, pb1);
                ffma2(acc[i][2], pa, pb2);
                ffma2(acc[i][3], pa, pb3);
            }
        }
        __syncthreads();
        if (has_next) {
            #pragma unroll
            for (int it = 0; it < 2; ++it) {
                int r = lrow + it * 64;
                As[lk4 + 0][r] = ra[it].x; As[lk4 + 1][r] = ra[it].y;
                As[lk4 + 2][r] = ra[it].z; As[lk4 + 3][r] = ra[it].w;
                Bs[lk4 + 0][r] = rb[it].x; Bs[lk4 + 1][r] = rb[it].y;
                Bs[lk4 + 2][r] = rb[it].z; Bs[lk4 + 3][r] = rb[it].w;
            }
            __syncthreads();
        }
    }

    // epilogue
    #pragma unroll
    for (int i = 0; i < 8; ++i) {
        int m = m0 + ((i < 4) ? (ty4 + i) : (64 + ty4 + i - 4));
        if (m >= M) continue;
        float v[8];
        #pragma unroll
        for (int j = 0; j < 4; ++j) {
            v[2 * j]     = __uint_as_float((unsigned int)(acc[i][j]));
            v[2 * j + 1] = __uint_as_float((unsigned int)(acc[i][j] >> 32));
        }
        if (MODE == 2) {
            int   s   = base + m;
            int   tok = d_tok[s];
            float w   = d_wt[s];
            float* orow = C + (size_t)tok * N;
            #pragma unroll
            for (int j = 0; j < 4; ++j)
                atomicAdd(&orow[n0 + tx4 + j], w * v[j]);
            #pragma unroll
            for (int j = 0; j < 4; ++j)
                atomicAdd(&orow[n0 + 64 + tx4 + j], w * v[4 + j]);
        } else {
            size_t crow = (MODE == 1) ? (size_t)(base + m) : (size_t)m;
            float* cp = C + crow * N;
            float4 s0 = make_float4(v[0], v[1], v[2], v[3]);
            float4 s1 = make_float4(v[4], v[5], v[6], v[7]);
            *(float4*)&cp[n0 + tx4]      = s0;
            *(float4*)&cp[n0 + 64 + tx4] = s1;
        }
    }
}

// ---------------- launch ----------------
extern "C" void kernel_launch(void* const* d_in, const int* in_sizes, int n_in,
                              void* d_out, int out_size) {
    const float* x   = (const float*)d_in[0];
    const float* gw  = (const float*)d_in[1];
    const float* eg  = (const float*)d_in[2];
    const float* eu  = (const float*)d_in[3];
    const float* ed  = (const float*)d_in[4];
    const float* sg  = (const float*)d_in[5];
    const float* su  = (const float*)d_in[6];
    const float* sd  = (const float*)d_in[7];
    float* out = (float*)d_out;

    float* buf1; float* buf2;
    cudaGetSymbolAddress((void**)&buf1, d_buf1);
    cudaGetSymbolAddress((void**)&buf2, d_buf2);

    // routing
    zero_kernel<<<1, 32>>>();
    router_kernel<<<N_TOK, 256>>>(x, gw);
    offsets_kernel<<<1, 32>>>();
    scatter_kernel<<<4, 256>>>();

    // shared expert (writes every element of out -> initializes it)
    gemm_nt<0><<<dim3(ISH / BN, N_TOK / BM, 1), 256>>>(x, sg, buf1, N_TOK, ISH, HDIM);
    gemm_nt<0><<<dim3(ISH / BN, N_TOK / BM, 1), 256>>>(x, su, buf2, N_TOK, ISH, HDIM);
    {
        int n = N_TOK * ISH;
        silu_mul_kernel<<<(n + 255) / 256, 256>>>(buf1, buf2, buf1, n);
    }
    gemm_nt<0><<<dim3(HDIM / BN, N_TOK / BM, 1), 256>>>(buf1, sd, out, N_TOK, HDIM, ISH);

    // routed experts (sparse: exactly 2048 token-expert slots)
    gemm_nt<1><<<dim3(IDIM / BN, N_TOK / BM, NEXP), 256>>>(x, eg, buf1, 0, IDIM, HDIM);
    gemm_nt<1><<<dim3(IDIM / BN, N_TOK / BM, NEXP), 256>>>(x, eu, buf2, 0, IDIM, HDIM);
    {
        int n = NSLOT * IDIM;
        silu_mul_kernel<<<(n + 255) / 256, 256>>>(buf1, buf2, buf1, n);
    }
    gemm_nt<2><<<dim3(HDIM / BN, N_TOK / BM, NEXP), 256>>>(buf1, ed, out, 0, HDIM, IDIM);
}